// round 11
// baseline (speedup 1.0000x reference)
#include <cuda_runtime.h>

#define NB 16
#define NN 4096
#define ND 64
#define NPOINT 1024
#define NSAMP 32
#define C0 67
#define O0 64
#define O1 64
#define O2 128
#define OUT_XYZ (NB*NPOINT*3)
#define GPB 8

#define SH 68   // hin row stride (floats, even -> 8B-aligned pairs)
#define SHP 34  // hin row stride in float2/u64 units
#define SG 132  // maxpool scratch stride

// -------- device scratch (no allocations allowed) --------
__device__ int   g_fps[NB * NPOINT];
__device__ int   g_grp[NB * NPOINT * NSAMP];
__device__ __align__(16) float g_W0p[34 * 64 * 2];   // [cp][o] float2 pairs (c,c+1); cp=33 -> (c66, 0)
__device__ __align__(16) float g_W1p[32 * 64 * 2];   // [cp][o] float2
__device__ __align__(16) float g_W2q[32 * 64 * 4];   // [cp][q] float4 = (w[2q][c],w[2q][c+1],w[2q+1][c],w[2q+1][c+1])
__device__ float g_b0f[O0];
__device__ float g_b1f[O1];
__device__ float g_b2f[O2];

// ---- packed f32x2 helpers (each lane: exact fp32 rn ops) ----
#define PACK2(out, lo, hi) \
    asm("mov.b64 %0, {%1, %2};" : "=l"(out) : "f"(lo), "f"(hi))
#define UNPACK2(lo, hi, in) \
    asm("mov.b64 {%0, %1}, %2;" : "=f"(lo), "=f"(hi) : "l"(in))
#define ADD2(out, a, b) \
    asm("add.rn.f32x2 %0, %1, %2;" : "=l"(out) : "l"(a), "l"(b))
#define MUL2(out, a, b) \
    asm("mul.rn.f32x2 %0, %1, %2;" : "=l"(out) : "l"(a), "l"(b))
#define FMA2(out, a, b, c) \
    asm("fma.rn.f32x2 %0, %1, %2, %3;" : "=l"(out) : "l"(a), "l"(b), "l"(c))
#define FMA2A(acc, a, b) \
    asm("fma.rn.f32x2 %0, %1, %2, %0;" : "+l"(acc) : "l"(a), "l"(b))

// ===================== BN fold (pair-packed weights) =====================
__global__ void fold_kernel(
    const float* __restrict__ W0, const float* __restrict__ b0, const float* __restrict__ g0,
    const float* __restrict__ be0, const float* __restrict__ m0, const float* __restrict__ v0,
    const float* __restrict__ W1, const float* __restrict__ b1, const float* __restrict__ g1,
    const float* __restrict__ be1, const float* __restrict__ m1, const float* __restrict__ v1,
    const float* __restrict__ W2, const float* __restrict__ b2, const float* __restrict__ g2,
    const float* __restrict__ be2, const float* __restrict__ m2, const float* __restrict__ v2)
{
    int t = threadIdx.x;
    int nt = blockDim.x;
    for (int e = t; e < 34 * 64; e += nt) {
        int cp = e >> 6, o = e & 63;
        float s = g0[o] * rsqrtf(v0[o] + 1e-5f);
        int c0 = 2 * cp, c1 = 2 * cp + 1;
        g_W0p[2 * e]     = W0[o * C0 + c0] * s;
        g_W0p[2 * e + 1] = (c1 < C0) ? W0[o * C0 + c1] * s : 0.0f;
    }
    for (int e = t; e < 32 * 64; e += nt) {
        int cp = e >> 6, o = e & 63;
        float s = g1[o] * rsqrtf(v1[o] + 1e-5f);
        g_W1p[2 * e]     = W1[o * O0 + 2 * cp] * s;
        g_W1p[2 * e + 1] = W1[o * O0 + 2 * cp + 1] * s;
    }
    for (int e = t; e < 32 * 64; e += nt) {
        int cp = e >> 6, q = e & 63;
        int o0 = 2 * q;
        float s0 = g2[o0] * rsqrtf(v2[o0] + 1e-5f);
        float s1 = g2[o0 + 1] * rsqrtf(v2[o0 + 1] + 1e-5f);
        g_W2q[4 * e]     = W2[o0 * O1 + 2 * cp] * s0;
        g_W2q[4 * e + 1] = W2[o0 * O1 + 2 * cp + 1] * s0;
        g_W2q[4 * e + 2] = W2[(o0 + 1) * O1 + 2 * cp] * s1;
        g_W2q[4 * e + 3] = W2[(o0 + 1) * O1 + 2 * cp + 1] * s1;
    }
    for (int o = t; o < O0; o += nt)
        g_b0f[o] = (b0[o] - m0[o]) * (g0[o] * rsqrtf(v0[o] + 1e-5f)) + be0[o];
    for (int o = t; o < O1; o += nt)
        g_b1f[o] = (b1[o] - m1[o]) * (g1[o] * rsqrtf(v1[o] + 1e-5f)) + be1[o];
    for (int o = t; o < O2; o += nt)
        g_b2f[o] = (b2[o] - m2[o]) * (g2[o] * rsqrtf(v2[o] + 1e-5f)) + be2[o];
}

// ===================== FPS (unchanged from R10 — measured good) =====================
__global__ __launch_bounds__(512) void fps_kernel(const float* __restrict__ xyz)
{
    __shared__ unsigned long long swk[2][16];

    int b = blockIdx.x;
    int t = threadIdx.x;
    int w = t >> 5;
    int lane = t & 31;
    const float* p = xyz + (size_t)b * NN * 3;

    float dl[8];
    unsigned long long px2[4], py2[4], pz2[4];
#pragma unroll
    for (int j = 0; j < 4; j++) {
        int p0 = t + (2 * j) * 512;
        int p1 = t + (2 * j + 1) * 512;
        float x0 = p[3 * p0], y0 = p[3 * p0 + 1], z0 = p[3 * p0 + 2];
        float x1 = p[3 * p1], y1 = p[3 * p1 + 1], z1 = p[3 * p1 + 2];
        PACK2(px2[j], x0, x1);
        PACK2(py2[j], y0, y1);
        PACK2(pz2[j], z0, z1);
        dl[2 * j] = 1e10f;
        dl[2 * j + 1] = 1e10f;
    }
    if (t == 0) g_fps[b * NPOINT] = 0;

    float cx = p[0], cy = p[1], cz = p[2];
    for (int it = 1; it < NPOINT; it++) {
        unsigned long long ncx2, ncy2, ncz2;
        {
            float nx = -cx, ny = -cy, nz = -cz;
            PACK2(ncx2, nx, nx);
            PACK2(ncy2, ny, ny);
            PACK2(ncz2, nz, nz);
        }
        float bv = -1.0f;
        int bi = 0;
#pragma unroll
        for (int j = 0; j < 4; j++) {
            unsigned long long dxp, dyp, dzp, dp;
            ADD2(dxp, px2[j], ncx2);          // x - cx  (== x + (-cx), exact)
            ADD2(dyp, py2[j], ncy2);
            ADD2(dzp, pz2[j], ncz2);
            MUL2(dp, dxp, dxp);
            FMA2(dp, dyp, dyp, dp);
            FMA2(dp, dzp, dzp, dp);
            float d0, d1;
            UNPACK2(d0, d1, dp);
            float dn0 = fminf(dl[2 * j], d0);
            dl[2 * j] = dn0;
            if (dn0 > bv) { bv = dn0; bi = t + (2 * j) * 512; }
            float dn1 = fminf(dl[2 * j + 1], d1);
            dl[2 * j + 1] = dn1;
            if (dn1 > bv) { bv = dn1; bi = t + (2 * j + 1) * 512; }
        }
        unsigned vb = __float_as_uint(bv);
        unsigned wmax = __reduce_max_sync(0xffffffffu, vb);
        unsigned cand = (vb == wmax) ? (unsigned)bi : 0xffffffffu;
        unsigned widx = __reduce_min_sync(0xffffffffu, cand);
        int par = it & 1;
        if (lane == 0)
            swk[par][w] = ((unsigned long long)wmax << 12) |
                          (unsigned)(4095 - widx);
        __syncthreads();
        unsigned long long k = swk[par][lane & 15];
#pragma unroll
        for (int off = 8; off > 0; off >>= 1) {
            unsigned long long ok = __shfl_xor_sync(0xffffffffu, k, off);
            if (ok > k) k = ok;
        }
        int idx = 4095 - (int)(k & 0xFFFu);
        cx = p[3 * idx]; cy = p[3 * idx + 1]; cz = p[3 * idx + 2];
        if (t == 0) g_fps[b * NPOINT + it] = idx;
    }
}

// ===================== ball query (+new_xyz write) =====================
__global__ __launch_bounds__(256) void ballquery_kernel(const float* __restrict__ xyz,
                                                        float* __restrict__ out)
{
    int gw = (blockIdx.x * 256 + threadIdx.x) >> 5;
    int lane = threadIdx.x & 31;
    if (gw >= NB * NPOINT) return;
    int b = gw >> 10;
    const float* p = xyz + (size_t)b * NN * 3;

    int ci = g_fps[gw];
    float cx = p[3 * ci + 0];
    float cy = p[3 * ci + 1];
    float cz = p[3 * ci + 2];
    if (lane < 3) out[(size_t)gw * 3 + lane] = p[3 * ci + lane];

    float sn = fmaf(cz, cz, fmaf(cy, cy, __fmul_rn(cx, cx)));
    int* grp = g_grp + (size_t)gw * NSAMP;

    int cnt = 0;
    int first = ci;
    bool gotfirst = false;
    for (int base = 0; base < NN && cnt < NSAMP; base += 32) {
        int i = base + lane;
        float x = p[3 * i + 0], y = p[3 * i + 1], z = p[3 * i + 2];
        float sp = fmaf(z, z, fmaf(y, y, __fmul_rn(x, x)));
        float dt = fmaf(cz, z, fmaf(cy, y, __fmul_rn(cx, x)));
        float d2 = fmaf(-2.0f, dt, sn + sp);
        bool isin = !(d2 > 0.04f);
        unsigned m = __ballot_sync(0xffffffffu, isin);
        if (!gotfirst && m) { first = base + __ffs(m) - 1; gotfirst = true; }
        int pos = cnt + __popc(m & ((1u << lane) - 1u));
        if (isin && pos < NSAMP) grp[pos] = i;
        cnt += __popc(m);
    }
    if (cnt < NSAMP) {
        int p0 = cnt + lane;
        if (p0 < NSAMP) grp[p0] = first;
    }
}

// ===================== fused gather + MLP(3) + maxpool, FMA2 mainloops ======
// Dot products split into (even-c) + (odd-c) partial sums via fma.rn.f32x2,
// combined at the end (valid: tolerance 1e-3, this adds ~1e-6).
// Layouts chosen so every LDS.64 is broadcast/contiguous -> conflict-free.
__global__ __launch_bounds__(128) void mlp_kernel(const float* __restrict__ xyz,
                                                  const float* __restrict__ pts,
                                                  float* __restrict__ out)
{
    __shared__ __align__(16) float sW0p[34 * 64 * 2];  // 4352 floats
    __shared__ __align__(16) float sW1p[32 * 64 * 2];  // 4096 floats
    __shared__ __align__(16) float hin[NSAMP * SH];    // 2176 ; reused as gmax[8][SG]
    __shared__ float sb[256];                          // b0|b1|b2
    __shared__ int   sidx[NSAMP];
    __shared__ float scen[3];

    int t = threadIdx.x;
    int kt = t >> 4;   // 0..7  (k = kt + 8*i)
    int ot = t & 15;   // 0..15

    {
        const float4* s0 = reinterpret_cast<const float4*>(g_W0p);
        float4* d0 = reinterpret_cast<float4*>(sW0p);
        for (int e = t; e < 34 * 64 * 2 / 4; e += 128) d0[e] = s0[e];
        const float4* s1 = reinterpret_cast<const float4*>(g_W1p);
        float4* d1 = reinterpret_cast<float4*>(sW1p);
        for (int e = t; e < 32 * 64 * 2 / 4; e += 128) d1[e] = s1[e];
    }
    if (t < 64) sb[t] = g_b0f[t];
    else        sb[t] = g_b1f[t - 64];
    for (int e = t; e < O2; e += 128) sb[128 + e] = g_b2f[e];
    __syncthreads();

    const unsigned long long* hin2 = reinterpret_cast<const unsigned long long*>(hin);
    const unsigned long long* w0p  = reinterpret_cast<const unsigned long long*>(sW0p);
    const unsigned long long* w1p  = reinterpret_cast<const unsigned long long*>(sW1p);
    const float4* W2q = reinterpret_cast<const float4*>(g_W2q);

    for (int g = 0; g < GPB; g++) {
        int gw = blockIdx.x * GPB + g;
        int b = gw >> 10;
        const float* pxyz = xyz + (size_t)b * NN * 3;
        const float* ppts = pts + (size_t)b * NN * ND;

        if (t < NSAMP) sidx[t] = g_grp[(size_t)gw * NSAMP + t];
        if (t < 3)     scen[t] = out[(size_t)gw * 3 + t];
        __syncthreads();

        // gather: hin[k][c] = c<3 ? xyz[id][c]-cen[c] : points[id][c-3]
        for (int e = t; e < NSAMP * C0; e += 128) {
            int k = e / C0;
            int c = e - k * C0;
            int id = sidx[k];
            float v;
            if (c < 3) v = pxyz[3 * id + c] - scen[c];
            else       v = ppts[(size_t)id * ND + (c - 3)];
            hin[k * SH + c] = v;
        }
        __syncthreads();

        // ---- Layer 0: 33 c-pairs (c 0..65) + scalar remainder c=66 ----
        {
            unsigned long long acc[4][4] = {};
            for (int cp = 0; cp < 33; cp++) {
                unsigned long long a2[4], w2[4];
#pragma unroll
                for (int i = 0; i < 4; i++) a2[i] = hin2[(kt + 8 * i) * SHP + cp];
#pragma unroll
                for (int j = 0; j < 4; j++) w2[j] = w0p[cp * 64 + ot + 16 * j];
#pragma unroll
                for (int i = 0; i < 4; i++)
#pragma unroll
                    for (int j = 0; j < 4; j++) FMA2A(acc[i][j], a2[i], w2[j]);
            }
            float ar[4], wr[4];
#pragma unroll
            for (int i = 0; i < 4; i++) ar[i] = hin[(kt + 8 * i) * SH + 66];
#pragma unroll
            for (int j = 0; j < 4; j++) wr[j] = sW0p[(33 * 64 + ot + 16 * j) * 2];
            float r[4][4];
#pragma unroll
            for (int i = 0; i < 4; i++)
#pragma unroll
                for (int j = 0; j < 4; j++) {
                    float lo, hi;
                    UNPACK2(lo, hi, acc[i][j]);
                    float s = fmaf(ar[i], wr[j], lo + hi);
                    r[i][j] = fmaxf(s + sb[ot + 16 * j], 0.0f);
                }
            __syncthreads();   // all reads of hin done
#pragma unroll
            for (int i = 0; i < 4; i++)
#pragma unroll
                for (int j = 0; j < 4; j++)
                    hin[(kt + 8 * i) * SH + ot + 16 * j] = r[i][j];
        }
        __syncthreads();

        // ---- Layer 1: 32 c-pairs ----
        {
            unsigned long long acc[4][4] = {};
            for (int cp = 0; cp < 32; cp++) {
                unsigned long long a2[4], w2[4];
#pragma unroll
                for (int i = 0; i < 4; i++) a2[i] = hin2[(kt + 8 * i) * SHP + cp];
#pragma unroll
                for (int j = 0; j < 4; j++) w2[j] = w1p[cp * 64 + ot + 16 * j];
#pragma unroll
                for (int i = 0; i < 4; i++)
#pragma unroll
                    for (int j = 0; j < 4; j++) FMA2A(acc[i][j], a2[i], w2[j]);
            }
            float r[4][4];
#pragma unroll
            for (int i = 0; i < 4; i++)
#pragma unroll
                for (int j = 0; j < 4; j++) {
                    float lo, hi;
                    UNPACK2(lo, hi, acc[i][j]);
                    r[i][j] = fmaxf((lo + hi) + sb[64 + ot + 16 * j], 0.0f);
                }
            __syncthreads();
#pragma unroll
            for (int i = 0; i < 4; i++)
#pragma unroll
                for (int j = 0; j < 4; j++)
                    hin[(kt + 8 * i) * SH + ot + 16 * j] = r[i][j];
        }
        __syncthreads();

        // ---- Layer 2: two o-passes (o = ot*8 + 4p + m), W2 from global float4;
        //      partial maxima kept in registers until hin reads complete ----
        {
            float pm[2][4];
#pragma unroll
            for (int p = 0; p < 2; p++) {
                unsigned long long acc[4][4] = {};
                for (int cp = 0; cp < 32; cp++) {
                    unsigned long long a2[4];
#pragma unroll
                    for (int i = 0; i < 4; i++) a2[i] = hin2[(kt + 8 * i) * SHP + cp];
                    float4 QA = __ldg(&W2q[cp * 64 + ot * 4 + 2 * p]);
                    float4 QB = __ldg(&W2q[cp * 64 + ot * 4 + 2 * p + 1]);
                    unsigned long long wq[4];
                    PACK2(wq[0], QA.x, QA.y);
                    PACK2(wq[1], QA.z, QA.w);
                    PACK2(wq[2], QB.x, QB.y);
                    PACK2(wq[3], QB.z, QB.w);
#pragma unroll
                    for (int i = 0; i < 4; i++)
#pragma unroll
                        for (int m = 0; m < 4; m++) FMA2A(acc[i][m], a2[i], wq[m]);
                }
#pragma unroll
                for (int m = 0; m < 4; m++) {
                    int o = ot * 8 + 4 * p + m;
                    float bias = sb[128 + o];
                    float lo, hi;
                    UNPACK2(lo, hi, acc[0][m]);
                    float v = fmaxf((lo + hi) + bias, 0.0f);
#pragma unroll
                    for (int i = 1; i < 4; i++) {
                        UNPACK2(lo, hi, acc[i][m]);
                        v = fmaxf(v, fmaxf((lo + hi) + bias, 0.0f));
                    }
                    pm[p][m] = v;
                }
            }
            __syncthreads();   // hin reads done; reuse as gmax[8][SG]
            float* gmax = hin;
#pragma unroll
            for (int p = 0; p < 2; p++)
#pragma unroll
                for (int m = 0; m < 4; m++)
                    gmax[kt * SG + ot * 8 + 4 * p + m] = pm[p][m];
            __syncthreads();
            float mx = gmax[t];
#pragma unroll
            for (int q = 1; q < 8; q++) mx = fmaxf(mx, gmax[q * SG + t]);
            out[OUT_XYZ + (size_t)gw * O2 + t] = mx;
        }
        __syncthreads();   // protect hin/sidx before next group's writes
    }
}

// ===================== launch =====================
extern "C" void kernel_launch(void* const* d_in, const int* in_sizes, int n_in,
                              void* d_out, int out_size)
{
    const float* xyz = (const float*)d_in[0];
    const float* pts = (const float*)d_in[1];
    const float* W0  = (const float*)d_in[2];
    const float* b0  = (const float*)d_in[3];
    const float* g0  = (const float*)d_in[4];
    const float* be0 = (const float*)d_in[5];
    const float* m0  = (const float*)d_in[6];
    const float* v0  = (const float*)d_in[7];
    const float* W1  = (const float*)d_in[8];
    const float* b1  = (const float*)d_in[9];
    const float* g1  = (const float*)d_in[10];
    const float* be1 = (const float*)d_in[11];
    const float* m1  = (const float*)d_in[12];
    const float* v1  = (const float*)d_in[13];
    const float* W2  = (const float*)d_in[14];
    const float* b2  = (const float*)d_in[15];
    const float* g2  = (const float*)d_in[16];
    const float* be2 = (const float*)d_in[17];
    const float* m2  = (const float*)d_in[18];
    const float* v2  = (const float*)d_in[19];
    float* out = (float*)d_out;

    // Kernel launches ONLY — graph-capturable. No dynamic smem, no attribute calls.
    fold_kernel<<<1, 256>>>(W0, b0, g0, be0, m0, v0,
                            W1, b1, g1, be1, m1, v1,
                            W2, b2, g2, be2, m2, v2);
    fps_kernel<<<NB, 512>>>(xyz);
    ballquery_kernel<<<(NB * NPOINT) / 8, 256>>>(xyz, out);
    mlp_kernel<<<(NB * NPOINT) / GPB, 128>>>(xyz, pts, out);
}

// round 12
// speedup vs baseline: 1.1722x; 1.1722x over previous
#include <cuda_runtime.h>

#define NB 16
#define NN 4096
#define ND 64
#define NPOINT 1024
#define NSAMP 32
#define C0 67
#define O0 64
#define O1 64
#define O2 128
#define OUT_XYZ (NB*NPOINT*3)
#define GPB 8

// smem strides (mlp, R5 layout)
#define S0 67   // W0 row stride
#define S1 65   // W1 row stride (odd -> conflict-free)
#define SH 68   // activation row stride
#define SG 132  // maxpool scratch stride

// -------- device scratch (no allocations allowed) --------
__device__ int   g_fps[NB * NPOINT];
__device__ int   g_grp[NB * NPOINT * NSAMP];
__device__ float g_W0f[O0 * C0];                 // [o][c]
__device__ float g_b0f[O0];
__device__ float g_W1f[O1 * O0];                 // [o][c]
__device__ float g_b1f[O1];
__device__ __align__(16) float g_W2t[O1 * O2];   // transposed [c][o]
__device__ float g_b2f[O2];

// ---- packed f32x2 helpers (each lane: exact fp32 rn ops) ----
#define PACK2(out, lo, hi) \
    asm("mov.b64 %0, {%1, %2};" : "=l"(out) : "f"(lo), "f"(hi))
#define UNPACK2(lo, hi, in) \
    asm("mov.b64 {%0, %1}, %2;" : "=f"(lo), "=f"(hi) : "l"(in))
#define ADD2(out, a, b) \
    asm("add.rn.f32x2 %0, %1, %2;" : "=l"(out) : "l"(a), "l"(b))
#define MUL2(out, a, b) \
    asm("mul.rn.f32x2 %0, %1, %2;" : "=l"(out) : "l"(a), "l"(b))
#define FMA2(out, a, b, c) \
    asm("fma.rn.f32x2 %0, %1, %2, %3;" : "=l"(out) : "l"(a), "l"(b), "l"(c))

// ===================== BN fold =====================
__global__ void fold_kernel(
    const float* __restrict__ W0, const float* __restrict__ b0, const float* __restrict__ g0,
    const float* __restrict__ be0, const float* __restrict__ m0, const float* __restrict__ v0,
    const float* __restrict__ W1, const float* __restrict__ b1, const float* __restrict__ g1,
    const float* __restrict__ be1, const float* __restrict__ m1, const float* __restrict__ v1,
    const float* __restrict__ W2, const float* __restrict__ b2, const float* __restrict__ g2,
    const float* __restrict__ be2, const float* __restrict__ m2, const float* __restrict__ v2)
{
    int t = threadIdx.x;
    int nt = blockDim.x;
    for (int e = t; e < O0 * C0; e += nt) {
        int o = e / C0;
        g_W0f[e] = W0[e] * (g0[o] * rsqrtf(v0[o] + 1e-5f));
    }
    for (int e = t; e < O1 * O0; e += nt) {
        int o = e >> 6;
        g_W1f[e] = W1[e] * (g1[o] * rsqrtf(v1[o] + 1e-5f));
    }
    for (int e = t; e < O2 * O1; e += nt) {
        int c = e >> 7;          // 0..63
        int o = e & 127;         // 0..127
        g_W2t[e] = W2[o * O1 + c] * (g2[o] * rsqrtf(v2[o] + 1e-5f));
    }
    for (int o = t; o < O0; o += nt)
        g_b0f[o] = (b0[o] - m0[o]) * (g0[o] * rsqrtf(v0[o] + 1e-5f)) + be0[o];
    for (int o = t; o < O1; o += nt)
        g_b1f[o] = (b1[o] - m1[o]) * (g1[o] * rsqrtf(v1[o] + 1e-5f)) + be1[o];
    for (int o = t; o < O2; o += nt)
        g_b2f[o] = (b2[o] - m2[o]) * (g2[o] * rsqrtf(v2[o] + 1e-5f)) + be2[o];
}

// ===================== FPS =====================
// 1024 threads (4 pts/thread). In-warp argmax via 32-bit REDUX; cross-warp via
// parity-buffered u32 val/idx arrays + ONE barrier + two 32-bit REDUX passes
// (replaces the 64-bit shuffle butterfly). Selections bit-identical.
__global__ __launch_bounds__(1024) void fps_kernel(const float* __restrict__ xyz)
{
    __shared__ unsigned swv[2][32];
    __shared__ unsigned swi[2][32];

    int b = blockIdx.x;
    int t = threadIdx.x;
    int w = t >> 5;
    int lane = t & 31;
    const float* p = xyz + (size_t)b * NN * 3;

    float dl[4];
    unsigned long long px2[2], py2[2], pz2[2];
#pragma unroll
    for (int j = 0; j < 2; j++) {
        int p0 = t + (2 * j) * 1024;
        int p1 = t + (2 * j + 1) * 1024;
        float x0 = p[3 * p0], y0 = p[3 * p0 + 1], z0 = p[3 * p0 + 2];
        float x1 = p[3 * p1], y1 = p[3 * p1 + 1], z1 = p[3 * p1 + 2];
        PACK2(px2[j], x0, x1);
        PACK2(py2[j], y0, y1);
        PACK2(pz2[j], z0, z1);
        dl[2 * j] = 1e10f;
        dl[2 * j + 1] = 1e10f;
    }
    if (t == 0) g_fps[b * NPOINT] = 0;

    float cx = p[0], cy = p[1], cz = p[2];
    for (int it = 1; it < NPOINT; it++) {
        unsigned long long ncx2, ncy2, ncz2;
        {
            float nx = -cx, ny = -cy, nz = -cz;
            PACK2(ncx2, nx, nx);
            PACK2(ncy2, ny, ny);
            PACK2(ncz2, nz, nz);
        }
        float bv = -1.0f;
        int bi = 0;
#pragma unroll
        for (int j = 0; j < 2; j++) {
            unsigned long long dxp, dyp, dzp, dp;
            ADD2(dxp, px2[j], ncx2);          // x - cx  (== x + (-cx), exact)
            ADD2(dyp, py2[j], ncy2);
            ADD2(dzp, pz2[j], ncz2);
            MUL2(dp, dxp, dxp);
            FMA2(dp, dyp, dyp, dp);
            FMA2(dp, dzp, dzp, dp);
            float d0, d1;
            UNPACK2(d0, d1, dp);
            float dn0 = fminf(dl[2 * j], d0);
            dl[2 * j] = dn0;
            if (dn0 > bv) { bv = dn0; bi = t + (2 * j) * 1024; }
            float dn1 = fminf(dl[2 * j + 1], d1);
            dl[2 * j + 1] = dn1;
            if (dn1 > bv) { bv = dn1; bi = t + (2 * j + 1) * 1024; }
        }
        // in-warp argmax: REDUX max on value bits (nonneg -> monotonic),
        // REDUX min over candidate indices (first-index ties exact).
        unsigned vb = __float_as_uint(bv);
        unsigned wmax = __reduce_max_sync(0xffffffffu, vb);
        unsigned cand = (vb == wmax) ? (unsigned)bi : 0xffffffffu;
        unsigned widx = __reduce_min_sync(0xffffffffu, cand);
        int par = it & 1;
        if (lane == 0) {
            swv[par][w] = wmax;
            swi[par][w] = widx;
        }
        __syncthreads();
        // cross-warp: each lane owns one warp slot; two 32-bit REDUX passes
        unsigned sv = swv[par][lane];
        unsigned gmax = __reduce_max_sync(0xffffffffu, sv);
        unsigned c2 = (sv == gmax) ? swi[par][lane] : 0xffffffffu;
        unsigned idx = __reduce_min_sync(0xffffffffu, c2);
        cx = p[3 * idx]; cy = p[3 * idx + 1]; cz = p[3 * idx + 2];  // uniform L1-hit
        if (t == 0) g_fps[b * NPOINT + it] = (int)idx;
    }
}

// ===================== ball query (+new_xyz write) =====================
__global__ __launch_bounds__(256) void ballquery_kernel(const float* __restrict__ xyz,
                                                        float* __restrict__ out)
{
    int gw = (blockIdx.x * 256 + threadIdx.x) >> 5;
    int lane = threadIdx.x & 31;
    if (gw >= NB * NPOINT) return;
    int b = gw >> 10;
    const float* p = xyz + (size_t)b * NN * 3;

    int ci = g_fps[gw];
    float cx = p[3 * ci + 0];
    float cy = p[3 * ci + 1];
    float cz = p[3 * ci + 2];
    if (lane < 3) out[(size_t)gw * 3 + lane] = p[3 * ci + lane];

    float sn = fmaf(cz, cz, fmaf(cy, cy, __fmul_rn(cx, cx)));
    int* grp = g_grp + (size_t)gw * NSAMP;

    int cnt = 0;
    int first = ci;
    bool gotfirst = false;
    for (int base = 0; base < NN && cnt < NSAMP; base += 32) {
        int i = base + lane;
        float x = p[3 * i + 0], y = p[3 * i + 1], z = p[3 * i + 2];
        float sp = fmaf(z, z, fmaf(y, y, __fmul_rn(x, x)));
        float dt = fmaf(cz, z, fmaf(cy, y, __fmul_rn(cx, x)));
        float d2 = fmaf(-2.0f, dt, sn + sp);
        bool isin = !(d2 > 0.04f);
        unsigned m = __ballot_sync(0xffffffffu, isin);
        if (!gotfirst && m) { first = base + __ffs(m) - 1; gotfirst = true; }
        int pos = cnt + __popc(m & ((1u << lane) - 1u));
        if (isin && pos < NSAMP) grp[pos] = i;
        cnt += __popc(m);
    }
    if (cnt < NSAMP) {
        int p0 = cnt + lane;
        if (p0 < NSAMP) grp[p0] = first;
    }
}

// ===================== fused gather + MLP(3) + maxpool =====================
// R5 version verbatim (measured 595.2/595.6 us twice — frozen best).
__global__ __launch_bounds__(128) void mlp_kernel(const float* __restrict__ xyz,
                                                  const float* __restrict__ pts,
                                                  float* __restrict__ out)
{
    __shared__ float sW0[O0 * S0];     // 4288 floats
    __shared__ float sW1[O1 * S1];     // 4160
    __shared__ float sb[256 + O2];     // [0,64)=b0 [64,128)=b1 [128,256)=b2
    __shared__ float hin[NSAMP * SH];  // 2176 ; reused as gmax[8][SG]
    __shared__ int   sidx[NSAMP];
    __shared__ float scen[3];

    int t = threadIdx.x;
    int kt = t >> 4;   // 0..7  (k = kt + 8*i)
    int ot = t & 15;   // 0..15

    for (int e = t; e < O0 * C0; e += 128) sW0[e] = g_W0f[e];
    for (int e = t; e < O1 * O0; e += 128) sW1[(e >> 6) * S1 + (e & 63)] = g_W1f[e];
    if (t < 64)       sb[t] = g_b0f[t];
    else              sb[t] = g_b1f[t - 64];
    for (int e = t; e < O2; e += 128) sb[128 + e] = g_b2f[e];
    __syncthreads();

    for (int g = 0; g < GPB; g++) {
        int gw = blockIdx.x * GPB + g;
        int b = gw >> 10;
        const float* pxyz = xyz + (size_t)b * NN * 3;
        const float* ppts = pts + (size_t)b * NN * ND;

        if (t < NSAMP) sidx[t] = g_grp[(size_t)gw * NSAMP + t];
        if (t < 3)     scen[t] = out[(size_t)gw * 3 + t];
        __syncthreads();

        // gather: hin[k][c] = c<3 ? xyz[id][c]-cen[c] : points[id][c-3]
        for (int e = t; e < NSAMP * C0; e += 128) {
            int k = e / C0;
            int c = e - k * C0;
            int id = sidx[k];
            float v;
            if (c < 3) v = pxyz[3 * id + c] - scen[c];
            else       v = ppts[(size_t)id * ND + (c - 3)];
            hin[k * SH + c] = v;
        }
        __syncthreads();

        // ---- Layer 0: [32,67] x W0[64,67]^T ; regs -> writeback into hin ----
        {
            float acc[4][4] = {};
            for (int c = 0; c < C0; c++) {
                float a[4], w[4];
#pragma unroll
                for (int i = 0; i < 4; i++) a[i] = hin[(kt + 8 * i) * SH + c];
#pragma unroll
                for (int j = 0; j < 4; j++) w[j] = sW0[(ot + 16 * j) * S0 + c];
#pragma unroll
                for (int i = 0; i < 4; i++)
#pragma unroll
                    for (int j = 0; j < 4; j++) acc[i][j] = fmaf(a[i], w[j], acc[i][j]);
            }
            __syncthreads();   // all reads of hin done
#pragma unroll
            for (int i = 0; i < 4; i++)
#pragma unroll
                for (int j = 0; j < 4; j++) {
                    int k = kt + 8 * i, o = ot + 16 * j;
                    hin[k * SH + o] = fmaxf(acc[i][j] + sb[o], 0.0f);
                }
        }
        __syncthreads();

        // ---- Layer 1: [32,64] x W1[64,64]^T ; regs -> writeback into hin ----
        {
            float acc[4][4] = {};
            for (int c = 0; c < O0; c++) {
                float a[4], w[4];
#pragma unroll
                for (int i = 0; i < 4; i++) a[i] = hin[(kt + 8 * i) * SH + c];
#pragma unroll
                for (int j = 0; j < 4; j++) w[j] = sW1[(ot + 16 * j) * S1 + c];
#pragma unroll
                for (int i = 0; i < 4; i++)
#pragma unroll
                    for (int j = 0; j < 4; j++) acc[i][j] = fmaf(a[i], w[j], acc[i][j]);
            }
            __syncthreads();
#pragma unroll
            for (int i = 0; i < 4; i++)
#pragma unroll
                for (int j = 0; j < 4; j++) {
                    int k = kt + 8 * i, o = ot + 16 * j;
                    hin[k * SH + o] = fmaxf(acc[i][j] + sb[64 + o], 0.0f);
                }
        }
        __syncthreads();

        // ---- Layer 2: [32,64] x W2t (global, transposed, float4, L1-resident),
        //      then max over k ----
        {
            float acc[4][8] = {};
            const float4* W2v = reinterpret_cast<const float4*>(g_W2t);
            for (int c = 0; c < O1; c++) {
                float a[4];
#pragma unroll
                for (int i = 0; i < 4; i++) a[i] = hin[(kt + 8 * i) * SH + c];
                float4 w0 = __ldg(&W2v[c * 32 + ot * 2 + 0]);
                float4 w1 = __ldg(&W2v[c * 32 + ot * 2 + 1]);
                float w[8] = {w0.x, w0.y, w0.z, w0.w, w1.x, w1.y, w1.z, w1.w};
#pragma unroll
                for (int i = 0; i < 4; i++)
#pragma unroll
                    for (int j = 0; j < 8; j++) acc[i][j] = fmaf(a[i], w[j], acc[i][j]);
            }
            __syncthreads();   // hin reads done; reuse as gmax[8][SG]
            float* gmax = hin;
#pragma unroll
            for (int j = 0; j < 8; j++) {
                int o = ot * 8 + j;
                float bias = sb[128 + o];
                float pm = fmaxf(acc[0][j] + bias, 0.0f);
#pragma unroll
                for (int i = 1; i < 4; i++)
                    pm = fmaxf(pm, fmaxf(acc[i][j] + bias, 0.0f));
                gmax[kt * SG + o] = pm;
            }
            __syncthreads();
            float mx = gmax[t];
#pragma unroll
            for (int q = 1; q < 8; q++) mx = fmaxf(mx, gmax[q * SG + t]);
            out[OUT_XYZ + (size_t)gw * O2 + t] = mx;
        }
        __syncthreads();   // protect hin/sidx before next group's writes
    }
}

// ===================== launch =====================
extern "C" void kernel_launch(void* const* d_in, const int* in_sizes, int n_in,
                              void* d_out, int out_size)
{
    const float* xyz = (const float*)d_in[0];
    const float* pts = (const float*)d_in[1];
    const float* W0  = (const float*)d_in[2];
    const float* b0  = (const float*)d_in[3];
    const float* g0  = (const float*)d_in[4];
    const float* be0 = (const float*)d_in[5];
    const float* m0  = (const float*)d_in[6];
    const float* v0  = (const float*)d_in[7];
    const float* W1  = (const float*)d_in[8];
    const float* b1  = (const float*)d_in[9];
    const float* g1  = (const float*)d_in[10];
    const float* be1 = (const float*)d_in[11];
    const float* m1  = (const float*)d_in[12];
    const float* v1  = (const float*)d_in[13];
    const float* W2  = (const float*)d_in[14];
    const float* b2  = (const float*)d_in[15];
    const float* g2  = (const float*)d_in[16];
    const float* be2 = (const float*)d_in[17];
    const float* m2  = (const float*)d_in[18];
    const float* v2  = (const float*)d_in[19];
    float* out = (float*)d_out;

    // Kernel launches ONLY — graph-capturable. No dynamic smem, no attribute calls.
    fold_kernel<<<1, 256>>>(W0, b0, g0, be0, m0, v0,
                            W1, b1, g1, be1, m1, v1,
                            W2, b2, g2, be2, m2, v2);
    fps_kernel<<<NB, 1024>>>(xyz);
    ballquery_kernel<<<(NB * NPOINT) / 8, 256>>>(xyz, out);
    mlp_kernel<<<(NB * NPOINT) / GPB, 128>>>(xyz, pts, out);
}